// round 10
// baseline (speedup 1.0000x reference)
#include <cuda_runtime.h>
#include <math_constants.h>

#define HH 1024
#define WW 1024
#define NCH 48
#define RSTRIP 16
#define SLICES (HH / RSTRIP)   // 64 row-slices per channel

// Per-(channel, row-slice) max of raw |det|. Every slot is written on every
// run by pass 1, so no init kernel and no atomics are needed.
__device__ float g_bmax[NCH * SLICES];

// det = gxx*gyy - gxy^2 reformulated:
//   t = a + c, C = a - c (a=row above, b=center, c=row below)
//   p = t[j] + t[j+2] - 4 b[j+1] ; r = b[j] + b[j+2] - t[j+1]
//   det = p^2 - (2r)^2 - gxy^2 ;  gxy = C[j+2] - C[j]

// ---------------------------------------------------------------------------
// Pass 1: per-slice max of raw scores. 8 score cols per thread.
// Prefetch (LDGs) is decoupled from expand (shuffles) to pipeline by 1 iter.
// ---------------------------------------------------------------------------
__device__ __forceinline__ void pre10(const float* __restrict__ row, int gc,
                                      int lane, int lcm1, int lcp8,
                                      float4& m0, float4& m1, float& e) {
    m0 = *reinterpret_cast<const float4*>(row + gc);
    m1 = *reinterpret_cast<const float4*>(row + gc + 4);
    if (lane == 0)  e = row[lcm1];
    if (lane == 31) e = row[lcp8];
}
__device__ __forceinline__ void exp10(float4 m0, float4 m1, float e,
                                      int lane, float u[10]) {
    u[1] = m0.x; u[2] = m0.y; u[3] = m0.z; u[4] = m0.w;
    u[5] = m1.x; u[6] = m1.y; u[7] = m1.z; u[8] = m1.w;
    u[0] = __shfl_up_sync(0xffffffffu, u[8], 1);
    u[9] = __shfl_down_sync(0xffffffffu, u[1], 1);
    if (lane == 0)  u[0] = e;
    if (lane == 31) u[9] = e;
}

__global__ __launch_bounds__(128, 8)
void max_kernel(const float* __restrict__ x) {
    __shared__ float wmax[4];
    const int ch = blockIdx.y;
    const int y0 = blockIdx.x * RSTRIP;
    const int gc = threadIdx.x * 8;
    const int lane = threadIdx.x & 31;
    const float* __restrict__ xc = x + (size_t)ch * (HH * WW);
    const int lcm1 = max(gc - 1, 0), lcp8 = min(gc + 8, WW - 1);

    float X[3][10];
    {
        float4 a0, a1; float ae = 0.0f;
        pre10(xc + max(y0 - 1, 0) * WW, gc, lane, lcm1, lcp8, a0, a1, ae);
        exp10(a0, a1, ae, lane, X[0]);
        pre10(xc + y0 * WW, gc, lane, lcm1, lcp8, a0, a1, ae);
        exp10(a0, a1, ae, lane, X[1]);
    }
    float4 F0, F1; float Fe = 0.0f;                 // pending row y0+1
    pre10(xc + min(y0 + 1, HH - 1) * WW, gc, lane, lcm1, lcp8, F0, F1, Fe);

    float m = 0.0f;
    #pragma unroll
    for (int i = 0; i < RSTRIP; i++) {
        exp10(F0, F1, Fe, lane, X[(i + 2) % 3]);    // row y0+i+1
        if (i < RSTRIP - 1) {
            const int ry = min(y0 + i + 2, HH - 1);
            pre10(xc + ry * WW, gc, lane, lcm1, lcp8, F0, F1, Fe);
        }
        const float* a = X[i % 3];
        const float* b = X[(i + 1) % 3];
        const float* c = X[(i + 2) % 3];

        float t[10], C[10];
        #pragma unroll
        for (int k = 0; k < 10; k++) { t[k] = a[k] + c[k]; C[k] = a[k] - c[k]; }

        #pragma unroll
        for (int j = 0; j < 8; j++) {
            float u = t[j] + t[j + 2];
            float p = fmaf(-4.0f, b[j + 1], u);
            float r = (b[j] + b[j + 2]) - t[j + 1];
            float r2 = r + r;
            float gxy = C[j + 2] - C[j];
            float m1 = fmaf(r2, r2, gxy * gxy);
            float det = fmaf(p, p, -m1);
            m = fmaxf(m, fabsf(det));
        }
    }

    #pragma unroll
    for (int off = 16; off > 0; off >>= 1)
        m = fmaxf(m, __shfl_xor_sync(0xffffffffu, m, off));
    if (lane == 0) wmax[threadIdx.x >> 5] = m;
    __syncthreads();
    if (threadIdx.x == 0) {
        m = fmaxf(fmaxf(wmax[0], wmax[1]), fmaxf(wmax[2], wmax[3]));
        g_bmax[ch * SLICES + blockIdx.x] = m;
    }
}

// ---------------------------------------------------------------------------
// Pass 2: scores + separable NMS + normalization, registers only.
// 4 output cols per thread; prefetch decoupled from expand, pipelined 1 iter.
// ---------------------------------------------------------------------------
__device__ __forceinline__ void pre8(const float* __restrict__ row, int gc,
                                     int lane, int lcm2, int lcm1,
                                     int lcp4, int lcp5,
                                     float4& m, float& e0, float& e1) {
    m = *reinterpret_cast<const float4*>(row + gc);
    if (lane == 0)  { e0 = row[lcm2]; e1 = row[lcm1]; }
    if (lane == 31) { e0 = row[lcp4]; e1 = row[lcp5]; }
}
__device__ __forceinline__ void exp8(float4 m, float e0, float e1,
                                     int lane, float v[8]) {
    v[2] = m.x; v[3] = m.y; v[4] = m.z; v[5] = m.w;
    v[0] = __shfl_up_sync(0xffffffffu, v[4], 1);
    v[1] = __shfl_up_sync(0xffffffffu, v[5], 1);
    v[6] = __shfl_down_sync(0xffffffffu, v[2], 1);
    v[7] = __shfl_down_sync(0xffffffffu, v[3], 1);
    if (lane == 0)  { v[0] = e0; v[1] = e1; }
    if (lane == 31) { v[6] = e0; v[7] = e1; }
}

__global__ __launch_bounds__(256, 6)
void hessian_kernel(const float* __restrict__ x, float* __restrict__ out) {
    __shared__ float redsm[2];
    const int ch = blockIdx.y;
    const int y0 = blockIdx.x * RSTRIP;
    const int gc = threadIdx.x * 4;
    const int lane = threadIdx.x & 31;
    const float* __restrict__ xc = x + (size_t)ch * (HH * WW);
    float* __restrict__ oc = out + (size_t)ch * (HH * WW);

    // Reduce the 64 per-slice maxima for this channel (L2-hit loads).
    if (threadIdx.x < SLICES) {
        float v = g_bmax[ch * SLICES + threadIdx.x];
        #pragma unroll
        for (int off = 16; off > 0; off >>= 1)
            v = fmaxf(v, __shfl_xor_sync(0xffffffffu, v, off));
        if ((threadIdx.x & 31) == 0) redsm[threadIdx.x >> 5] = v;
    }
    __syncthreads();
    const float inv = 1.0f / fmaxf(fmaxf(redsm[0], redsm[1]), 1e-6f);

    const int lcm2 = max(gc - 2, 0), lcm1 = max(gc - 1, 0);
    const int lcp4 = min(gc + 4, WW - 1), lcp5 = min(gc + 5, WW - 1);

    float X[3][8];                 // x rows, cols gc-2..gc+5
    float s1[6], s2[6];            // previous two score rows (cols gc-1..gc+4)
    #pragma unroll
    for (int k = 0; k < 6; k++) { s1[k] = 0.0f; s2[k] = 0.0f; }

    {
        float4 a; float e0 = 0.0f, e1 = 0.0f;
        pre8(xc + max(y0 - 2, 0) * WW, gc, lane, lcm2, lcm1, lcp4, lcp5, a, e0, e1);
        exp8(a, e0, e1, lane, X[0]);
        pre8(xc + max(y0 - 1, 0) * WW, gc, lane, lcm2, lcm1, lcp4, lcp5, a, e0, e1);
        exp8(a, e0, e1, lane, X[1]);
    }
    float4 F; float Fe0 = 0.0f, Fe1 = 0.0f;         // pending row y0
    pre8(xc + y0 * WW, gc, lane, lcm2, lcm1, lcp4, lcp5, F, Fe0, Fe1);

    #pragma unroll
    for (int i = 0; i < RSTRIP + 2; i++) {
        const int sr = y0 - 1 + i;                  // score row produced this iter
        exp8(F, Fe0, Fe1, lane, X[(2 + i) % 3]);    // row y0+i
        if (i < RSTRIP + 1) {
            const int ry = min(y0 + i + 1, HH - 1);
            pre8(xc + ry * WW, gc, lane, lcm2, lcm1, lcp4, lcp5, F, Fe0, Fe1);
        }
        const float* a = X[i % 3];
        const float* b = X[(i + 1) % 3];
        const float* c = X[(i + 2) % 3];

        float t[8], C[8];
        #pragma unroll
        for (int k = 0; k < 8; k++) { t[k] = a[k] + c[k]; C[k] = a[k] - c[k]; }

        float sc6[6];
        #pragma unroll
        for (int j = 0; j < 6; j++) {               // score cols gc-1+j
            float u = t[j] + t[j + 2];
            float p = fmaf(-4.0f, b[j + 1], u);
            float r = (b[j] + b[j + 2]) - t[j + 1];
            float r2 = r + r;
            float gxy = C[j + 2] - C[j];
            float m1 = fmaf(r2, r2, gxy * gxy);
            float det = fmaf(p, p, -m1);
            sc6[j] = fmaxf(fabsf(det), 1e-6f);
        }
        // Column edges: score col -1 (thread 0) / col 1024 (thread 255).
        if (gc == 0)       sc6[0] = -CUDART_INF_F;
        if (gc == WW - 4)  sc6[5] = -CUDART_INF_F;
        // Row edges: only possible at unrolled iters 0 and RSTRIP+1.
        if ((i == 0 && sr < 0) || (i == RSTRIP + 1 && sr >= HH)) {
            #pragma unroll
            for (int k = 0; k < 6; k++) sc6[k] = -CUDART_INF_F;
        }

        if (i >= 2) {
            const int y = sr - 1;                   // output row
            float cm[6];
            #pragma unroll
            for (int k = 0; k < 6; k++)
                cm[k] = fmaxf(fmaxf(s2[k], s1[k]), sc6[k]);
            float ov[4];
            #pragma unroll
            for (int k = 0; k < 4; k++) {
                float pmax = fmaxf(fmaxf(cm[k], cm[k + 1]), cm[k + 2]);
                float sv = s1[k + 1];
                ov[k] = (sv == pmax) ? sv * inv : 0.0f;
            }
            float4 o; o.x = ov[0]; o.y = ov[1]; o.z = ov[2]; o.w = ov[3];
            *reinterpret_cast<float4*>(oc + (size_t)y * WW + gc) = o;
        }

        #pragma unroll
        for (int k = 0; k < 6; k++) { s2[k] = s1[k]; s1[k] = sc6[k]; }
    }
}

extern "C" void kernel_launch(void* const* d_in, const int* in_sizes, int n_in,
                              void* d_out, int out_size) {
    const float* x = (const float*)d_in[0];
    float* out = (float*)d_out;

    dim3 mgrd(SLICES, NCH);
    max_kernel<<<mgrd, 128>>>(x);

    dim3 hgrd(HH / RSTRIP, NCH);
    hessian_kernel<<<hgrd, 256>>>(x, out);
}

// round 11
// speedup vs baseline: 1.1665x; 1.1665x over previous
#include <cuda_runtime.h>
#include <math_constants.h>

#define HH 1024
#define WW 1024
#define NCH 48
#define RSTRIP 16
#define SLICES (HH / RSTRIP)   // 64 row-slices per channel

// Per-(channel, row-slice) max of raw |det|. Every slot is written on every
// run by pass 1, so no init kernel and no atomics are needed.
__device__ float g_bmax[NCH * SLICES];

// det = gxx*gyy - gxy^2 reformulated:
//   t = a + c, C = a - c (a=row above, b=center, c=row below)
//   p = t[j] + t[j+2] - 4 b[j+1] ; r = b[j] + b[j+2] - t[j+1]
//   det = p^2 - (2r)^2 - gxy^2 ;  gxy = C[j+2] - C[j]

// ---------------------------------------------------------------------------
// Pass 1: per-slice max of raw scores. 8 score cols per thread. (R7 version)
// ---------------------------------------------------------------------------
__device__ __forceinline__ void ldrow10(const float* __restrict__ row, int gc,
                                        int lane, float u[10]) {
    float4 m0 = *reinterpret_cast<const float4*>(row + gc);
    float4 m1 = *reinterpret_cast<const float4*>(row + gc + 4);
    u[1] = m0.x; u[2] = m0.y; u[3] = m0.z; u[4] = m0.w;
    u[5] = m1.x; u[6] = m1.y; u[7] = m1.z; u[8] = m1.w;
    u[0] = __shfl_up_sync(0xffffffffu, u[8], 1);
    u[9] = __shfl_down_sync(0xffffffffu, u[1], 1);
    if (lane == 0)  u[0] = row[max(gc - 1, 0)];
    if (lane == 31) u[9] = row[min(gc + 8, WW - 1)];
}

__global__ __launch_bounds__(128, 8)
void max_kernel(const float* __restrict__ x) {
    __shared__ float wmax[4];
    const int ch = blockIdx.y;
    const int y0 = blockIdx.x * RSTRIP;
    const int gc = threadIdx.x * 8;
    const int lane = threadIdx.x & 31;
    const float* __restrict__ xc = x + (size_t)ch * (HH * WW);

    float X[3][10];
    ldrow10(xc + max(y0 - 1, 0) * WW, gc, lane, X[0]);
    ldrow10(xc + y0 * WW, gc, lane, X[1]);

    float m = 0.0f;
    #pragma unroll
    for (int i = 0; i < RSTRIP; i++) {
        const int ry = min(y0 + i + 1, HH - 1);
        ldrow10(xc + ry * WW, gc, lane, X[(i + 2) % 3]);
        const float* a = X[i % 3];
        const float* b = X[(i + 1) % 3];
        const float* c = X[(i + 2) % 3];

        float t[10], C[10];
        #pragma unroll
        for (int k = 0; k < 10; k++) { t[k] = a[k] + c[k]; C[k] = a[k] - c[k]; }

        #pragma unroll
        for (int j = 0; j < 8; j++) {
            float u = t[j] + t[j + 2];
            float p = fmaf(-4.0f, b[j + 1], u);
            float r = (b[j] + b[j + 2]) - t[j + 1];
            float r2 = r + r;
            float gxy = C[j + 2] - C[j];
            float m1 = fmaf(r2, r2, gxy * gxy);
            float det = fmaf(p, p, -m1);
            m = fmaxf(m, fabsf(det));
        }
    }

    #pragma unroll
    for (int off = 16; off > 0; off >>= 1)
        m = fmaxf(m, __shfl_xor_sync(0xffffffffu, m, off));
    if (lane == 0) wmax[threadIdx.x >> 5] = m;
    __syncthreads();
    if (threadIdx.x == 0) {
        m = fmaxf(fmaxf(wmax[0], wmax[1]), fmaxf(wmax[2], wmax[3]));
        g_bmax[ch * SLICES + blockIdx.x] = m;
    }
}

// ---------------------------------------------------------------------------
// Pass 2: scores + separable NMS + normalization, registers only.
// Each thread: 8 output cols (gc..gc+7); x cols gc-2..gc+9 (v[k] = x[gc-2+k]).
// ---------------------------------------------------------------------------
__device__ __forceinline__ void ldrow12(const float* __restrict__ row, int gc,
                                        int lane, int lcm2, int lcm1,
                                        int lcp8, int lcp9, float v[12]) {
    float4 m0 = *reinterpret_cast<const float4*>(row + gc);
    float4 m1 = *reinterpret_cast<const float4*>(row + gc + 4);
    v[2] = m0.x; v[3] = m0.y; v[4] = m0.z; v[5] = m0.w;
    v[6] = m1.x; v[7] = m1.y; v[8] = m1.z; v[9] = m1.w;
    v[0]  = __shfl_up_sync(0xffffffffu, v[8], 1);   // prev lane x[gc-2]
    v[1]  = __shfl_up_sync(0xffffffffu, v[9], 1);   // prev lane x[gc-1]
    v[10] = __shfl_down_sync(0xffffffffu, v[2], 1); // next lane x[gc+8]
    v[11] = __shfl_down_sync(0xffffffffu, v[3], 1); // next lane x[gc+9]
    if (lane == 0)  { v[0]  = row[lcm2]; v[1]  = row[lcm1]; }
    if (lane == 31) { v[10] = row[lcp8]; v[11] = row[lcp9]; }
}

__global__ __launch_bounds__(128, 6)
void hessian_kernel(const float* __restrict__ x, float* __restrict__ out) {
    __shared__ float redsm[2];
    const int ch = blockIdx.y;
    const int y0 = blockIdx.x * RSTRIP;
    const int gc = threadIdx.x * 8;
    const int lane = threadIdx.x & 31;
    const float* __restrict__ xc = x + (size_t)ch * (HH * WW);
    float* __restrict__ oc = out + (size_t)ch * (HH * WW);

    // Reduce the 64 per-slice maxima for this channel (L2-hit loads).
    if (threadIdx.x < SLICES) {
        float v = g_bmax[ch * SLICES + threadIdx.x];
        #pragma unroll
        for (int off = 16; off > 0; off >>= 1)
            v = fmaxf(v, __shfl_xor_sync(0xffffffffu, v, off));
        if ((threadIdx.x & 31) == 0) redsm[threadIdx.x >> 5] = v;
    }
    __syncthreads();
    const float inv = 1.0f / fmaxf(fmaxf(redsm[0], redsm[1]), 1e-6f);

    const int lcm2 = max(gc - 2, 0), lcm1 = max(gc - 1, 0);
    const int lcp8 = min(gc + 8, WW - 1), lcp9 = min(gc + 9, WW - 1);

    float X[3][12];                // x rows, cols gc-2..gc+9
    float s1[10], s2[10];          // previous two score rows (cols gc-1..gc+8)
    #pragma unroll
    for (int k = 0; k < 10; k++) { s1[k] = 0.0f; s2[k] = 0.0f; }

    ldrow12(xc + max(y0 - 2, 0) * WW, gc, lane, lcm2, lcm1, lcp8, lcp9, X[0]);
    ldrow12(xc + max(y0 - 1, 0) * WW, gc, lane, lcm2, lcm1, lcp8, lcp9, X[1]);

    #pragma unroll
    for (int i = 0; i < RSTRIP + 2; i++) {
        const int sr = y0 - 1 + i;                  // score row produced this iter
        const int ry = min(y0 + i, HH - 1);
        ldrow12(xc + ry * WW, gc, lane, lcm2, lcm1, lcp8, lcp9, X[(2 + i) % 3]);
        const float* a = X[i % 3];
        const float* b = X[(i + 1) % 3];
        const float* c = X[(i + 2) % 3];

        float t[12], C[12];
        #pragma unroll
        for (int k = 0; k < 12; k++) { t[k] = a[k] + c[k]; C[k] = a[k] - c[k]; }

        float sc[10];
        #pragma unroll
        for (int j = 0; j < 10; j++) {              // score cols gc-1+j
            float u = t[j] + t[j + 2];
            float p = fmaf(-4.0f, b[j + 1], u);
            float r = (b[j] + b[j + 2]) - t[j + 1];
            float r2 = r + r;
            float gxy = C[j + 2] - C[j];
            float m1 = fmaf(r2, r2, gxy * gxy);
            float det = fmaf(p, p, -m1);
            sc[j] = fmaxf(fabsf(det), 1e-6f);
        }
        // Column edges: score col -1 (thread 0) / col 1024 (thread 127).
        if (gc == 0)       sc[0] = -CUDART_INF_F;
        if (gc == WW - 8)  sc[9] = -CUDART_INF_F;
        // Row edges: only possible at unrolled iters 0 and RSTRIP+1.
        if ((i == 0 && sr < 0) || (i == RSTRIP + 1 && sr >= HH)) {
            #pragma unroll
            for (int k = 0; k < 10; k++) sc[k] = -CUDART_INF_F;
        }

        if (i >= 2) {
            const int y = sr - 1;                   // output row
            float cm[10];
            #pragma unroll
            for (int k = 0; k < 10; k++)
                cm[k] = fmaxf(fmaxf(s2[k], s1[k]), sc[k]);
            float ov[8];
            #pragma unroll
            for (int k = 0; k < 8; k++) {
                float pmax = fmaxf(fmaxf(cm[k], cm[k + 1]), cm[k + 2]);
                float sv = s1[k + 1];
                ov[k] = (sv == pmax) ? sv * inv : 0.0f;
            }
            float4 o0, o1;
            o0.x = ov[0]; o0.y = ov[1]; o0.z = ov[2]; o0.w = ov[3];
            o1.x = ov[4]; o1.y = ov[5]; o1.z = ov[6]; o1.w = ov[7];
            float* orow = oc + (size_t)y * WW + gc;
            *reinterpret_cast<float4*>(orow) = o0;
            *reinterpret_cast<float4*>(orow + 4) = o1;
        }

        #pragma unroll
        for (int k = 0; k < 10; k++) { s2[k] = s1[k]; s1[k] = sc[k]; }
    }
}

extern "C" void kernel_launch(void* const* d_in, const int* in_sizes, int n_in,
                              void* d_out, int out_size) {
    const float* x = (const float*)d_in[0];
    float* out = (float*)d_out;

    dim3 mgrd(SLICES, NCH);
    max_kernel<<<mgrd, 128>>>(x);

    dim3 hgrd(HH / RSTRIP, NCH);
    hessian_kernel<<<hgrd, 128>>>(x, out);
}

// round 12
// speedup vs baseline: 1.1710x; 1.0039x over previous
#include <cuda_runtime.h>
#include <math_constants.h>

#define HH 1024
#define WW 1024
#define NCH 48
#define RSTRIP 16
#define SLICES (HH / RSTRIP)   // 64 row-slices per channel

// Per-(channel, row-slice) max of raw |det|. Every slot is written on every
// run by pass 1, so no init kernel and no atomics are needed.
__device__ float g_bmax[NCH * SLICES];

// det = gxx*gyy - gxy^2 reformulated:
//   t = a + c, C = a - c (a=row above, b=center, c=row below)
//   p = t[j] + t[j+2] - 4 b[j+1] ; r = b[j] + b[j+2] - t[j+1]
//   det = p^2 - (2r)^2 - gxy^2 ;  gxy = C[j+2] - C[j]

// ---------------------------------------------------------------------------
// Pass 1: per-slice max of raw scores. 16 score cols per thread (64 thr/blk).
// u[j] = x[gc-1+j], j=0..17: 4 aligned float4 + 2 halo via lane shuffles.
// ---------------------------------------------------------------------------
__device__ __forceinline__ void ldrow18(const float* __restrict__ row, int gc,
                                        int lane, float u[18]) {
    float4 m0 = *reinterpret_cast<const float4*>(row + gc);
    float4 m1 = *reinterpret_cast<const float4*>(row + gc + 4);
    float4 m2 = *reinterpret_cast<const float4*>(row + gc + 8);
    float4 m3 = *reinterpret_cast<const float4*>(row + gc + 12);
    u[1]  = m0.x; u[2]  = m0.y; u[3]  = m0.z; u[4]  = m0.w;
    u[5]  = m1.x; u[6]  = m1.y; u[7]  = m1.z; u[8]  = m1.w;
    u[9]  = m2.x; u[10] = m2.y; u[11] = m2.z; u[12] = m2.w;
    u[13] = m3.x; u[14] = m3.y; u[15] = m3.z; u[16] = m3.w;
    u[0]  = __shfl_up_sync(0xffffffffu, u[16], 1);  // prev lane x[gc-1]
    u[17] = __shfl_down_sync(0xffffffffu, u[1], 1); // next lane x[gc+16]
    if (lane == 0)  u[0]  = row[max(gc - 1, 0)];    // also covers warp boundary
    if (lane == 31) u[17] = row[min(gc + 16, WW - 1)];
}

__global__ __launch_bounds__(64, 8)
void max_kernel(const float* __restrict__ x) {
    __shared__ float wmax[2];
    const int ch = blockIdx.y;
    const int y0 = blockIdx.x * RSTRIP;
    const int gc = threadIdx.x * 16;
    const int lane = threadIdx.x & 31;
    const float* __restrict__ xc = x + (size_t)ch * (HH * WW);

    float X[3][18];
    ldrow18(xc + max(y0 - 1, 0) * WW, gc, lane, X[0]);
    ldrow18(xc + y0 * WW, gc, lane, X[1]);

    float m = 0.0f;
    #pragma unroll
    for (int i = 0; i < RSTRIP; i++) {
        const int ry = min(y0 + i + 1, HH - 1);
        ldrow18(xc + ry * WW, gc, lane, X[(i + 2) % 3]);
        const float* a = X[i % 3];
        const float* b = X[(i + 1) % 3];
        const float* c = X[(i + 2) % 3];

        float t[18], C[18];
        #pragma unroll
        for (int k = 0; k < 18; k++) { t[k] = a[k] + c[k]; C[k] = a[k] - c[k]; }

        #pragma unroll
        for (int j = 0; j < 16; j++) {              // score cols gc+j
            float u = t[j] + t[j + 2];
            float p = fmaf(-4.0f, b[j + 1], u);
            float r = (b[j] + b[j + 2]) - t[j + 1];
            float r2 = r + r;
            float gxy = C[j + 2] - C[j];
            float m1 = fmaf(r2, r2, gxy * gxy);
            float det = fmaf(p, p, -m1);
            m = fmaxf(m, fabsf(det));
        }
    }

    #pragma unroll
    for (int off = 16; off > 0; off >>= 1)
        m = fmaxf(m, __shfl_xor_sync(0xffffffffu, m, off));
    if (lane == 0) wmax[threadIdx.x >> 5] = m;
    __syncthreads();
    if (threadIdx.x == 0)
        g_bmax[ch * SLICES + blockIdx.x] = fmaxf(wmax[0], wmax[1]);
}

// ---------------------------------------------------------------------------
// Pass 2: scores + separable NMS + normalization, registers only.
// Each thread: 8 output cols (gc..gc+7); x cols gc-2..gc+9 (v[k] = x[gc-2+k]).
// Channels processed in REVERSE order so hessian's first reads hit the x data
// max_kernel most recently streamed through L2.
// ---------------------------------------------------------------------------
__device__ __forceinline__ void ldrow12(const float* __restrict__ row, int gc,
                                        int lane, int lcm2, int lcm1,
                                        int lcp8, int lcp9, float v[12]) {
    float4 m0 = *reinterpret_cast<const float4*>(row + gc);
    float4 m1 = *reinterpret_cast<const float4*>(row + gc + 4);
    v[2] = m0.x; v[3] = m0.y; v[4] = m0.z; v[5] = m0.w;
    v[6] = m1.x; v[7] = m1.y; v[8] = m1.z; v[9] = m1.w;
    v[0]  = __shfl_up_sync(0xffffffffu, v[8], 1);   // prev lane x[gc-2]
    v[1]  = __shfl_up_sync(0xffffffffu, v[9], 1);   // prev lane x[gc-1]
    v[10] = __shfl_down_sync(0xffffffffu, v[2], 1); // next lane x[gc+8]
    v[11] = __shfl_down_sync(0xffffffffu, v[3], 1); // next lane x[gc+9]
    if (lane == 0)  { v[0]  = row[lcm2]; v[1]  = row[lcm1]; }
    if (lane == 31) { v[10] = row[lcp8]; v[11] = row[lcp9]; }
}

__global__ __launch_bounds__(128, 6)
void hessian_kernel(const float* __restrict__ x, float* __restrict__ out) {
    __shared__ float redsm[2];
    const int ch = (NCH - 1) - blockIdx.y;          // reverse channel order
    const int y0 = blockIdx.x * RSTRIP;
    const int gc = threadIdx.x * 8;
    const int lane = threadIdx.x & 31;
    const float* __restrict__ xc = x + (size_t)ch * (HH * WW);
    float* __restrict__ oc = out + (size_t)ch * (HH * WW);

    // Reduce the 64 per-slice maxima for this channel (L2-hit loads).
    if (threadIdx.x < SLICES) {
        float v = g_bmax[ch * SLICES + threadIdx.x];
        #pragma unroll
        for (int off = 16; off > 0; off >>= 1)
            v = fmaxf(v, __shfl_xor_sync(0xffffffffu, v, off));
        if ((threadIdx.x & 31) == 0) redsm[threadIdx.x >> 5] = v;
    }
    __syncthreads();
    const float inv = 1.0f / fmaxf(fmaxf(redsm[0], redsm[1]), 1e-6f);

    const int lcm2 = max(gc - 2, 0), lcm1 = max(gc - 1, 0);
    const int lcp8 = min(gc + 8, WW - 1), lcp9 = min(gc + 9, WW - 1);

    float X[3][12];                // x rows, cols gc-2..gc+9
    float s1[10], s2[10];          // previous two score rows (cols gc-1..gc+8)
    #pragma unroll
    for (int k = 0; k < 10; k++) { s1[k] = 0.0f; s2[k] = 0.0f; }

    ldrow12(xc + max(y0 - 2, 0) * WW, gc, lane, lcm2, lcm1, lcp8, lcp9, X[0]);
    ldrow12(xc + max(y0 - 1, 0) * WW, gc, lane, lcm2, lcm1, lcp8, lcp9, X[1]);

    #pragma unroll
    for (int i = 0; i < RSTRIP + 2; i++) {
        const int sr = y0 - 1 + i;                  // score row produced this iter
        const int ry = min(y0 + i, HH - 1);
        ldrow12(xc + ry * WW, gc, lane, lcm2, lcm1, lcp8, lcp9, X[(2 + i) % 3]);
        const float* a = X[i % 3];
        const float* b = X[(i + 1) % 3];
        const float* c = X[(i + 2) % 3];

        float t[12], C[12];
        #pragma unroll
        for (int k = 0; k < 12; k++) { t[k] = a[k] + c[k]; C[k] = a[k] - c[k]; }

        float sc[10];
        #pragma unroll
        for (int j = 0; j < 10; j++) {              // score cols gc-1+j
            float u = t[j] + t[j + 2];
            float p = fmaf(-4.0f, b[j + 1], u);
            float r = (b[j] + b[j + 2]) - t[j + 1];
            float r2 = r + r;
            float gxy = C[j + 2] - C[j];
            float m1 = fmaf(r2, r2, gxy * gxy);
            float det = fmaf(p, p, -m1);
            sc[j] = fmaxf(fabsf(det), 1e-6f);
        }
        // Column edges: score col -1 (thread 0) / col 1024 (thread 127).
        if (gc == 0)       sc[0] = -CUDART_INF_F;
        if (gc == WW - 8)  sc[9] = -CUDART_INF_F;
        // Row edges: only possible at unrolled iters 0 and RSTRIP+1.
        if ((i == 0 && sr < 0) || (i == RSTRIP + 1 && sr >= HH)) {
            #pragma unroll
            for (int k = 0; k < 10; k++) sc[k] = -CUDART_INF_F;
        }

        if (i >= 2) {
            const int y = sr - 1;                   // output row
            float cm[10];
            #pragma unroll
            for (int k = 0; k < 10; k++)
                cm[k] = fmaxf(fmaxf(s2[k], s1[k]), sc[k]);
            float ov[8];
            #pragma unroll
            for (int k = 0; k < 8; k++) {
                float pmax = fmaxf(fmaxf(cm[k], cm[k + 1]), cm[k + 2]);
                float sv = s1[k + 1];
                ov[k] = (sv == pmax) ? sv * inv : 0.0f;
            }
            float4 o0, o1;
            o0.x = ov[0]; o0.y = ov[1]; o0.z = ov[2]; o0.w = ov[3];
            o1.x = ov[4]; o1.y = ov[5]; o1.z = ov[6]; o1.w = ov[7];
            float* orow = oc + (size_t)y * WW + gc;
            *reinterpret_cast<float4*>(orow) = o0;
            *reinterpret_cast<float4*>(orow + 4) = o1;
        }

        #pragma unroll
        for (int k = 0; k < 10; k++) { s2[k] = s1[k]; s1[k] = sc[k]; }
    }
}

extern "C" void kernel_launch(void* const* d_in, const int* in_sizes, int n_in,
                              void* d_out, int out_size) {
    const float* x = (const float*)d_in[0];
    float* out = (float*)d_out;

    dim3 mgrd(SLICES, NCH);
    max_kernel<<<mgrd, 64>>>(x);

    dim3 hgrd(HH / RSTRIP, NCH);
    hessian_kernel<<<hgrd, 128>>>(x, out);
}

// round 13
// speedup vs baseline: 1.2737x; 1.0876x over previous
#include <cuda_runtime.h>
#include <math_constants.h>

#define HH 1024
#define WW 1024
#define NCH 48
#define RSTRIP 16
#define SLICES (HH / RSTRIP)   // 64 row-slices per channel

// Per-(channel, row-slice) max of raw |det|. Every slot is written on every
// run by pass 1, so no init kernel and no atomics are needed.
__device__ float g_bmax[NCH * SLICES];

// det = gxx*gyy - gxy^2 reformulated:
//   t = a + c, C = a - c (a=row above, b=center, c=row below)
//   p = t[j] + t[j+2] - 4 b[j+1] ; r = b[j] + b[j+2] - t[j+1]
//   det = p^2 - (2r)^2 - gxy^2 ;  gxy = C[j+2] - C[j]

// ---------------------------------------------------------------------------
// Pass 1: per-slice max of raw scores. 8 score cols per thread (R11 version).
// ---------------------------------------------------------------------------
__device__ __forceinline__ void ldrow10(const float* __restrict__ row, int gc,
                                        int lane, float u[10]) {
    float4 m0 = *reinterpret_cast<const float4*>(row + gc);
    float4 m1 = *reinterpret_cast<const float4*>(row + gc + 4);
    u[1] = m0.x; u[2] = m0.y; u[3] = m0.z; u[4] = m0.w;
    u[5] = m1.x; u[6] = m1.y; u[7] = m1.z; u[8] = m1.w;
    u[0] = __shfl_up_sync(0xffffffffu, u[8], 1);
    u[9] = __shfl_down_sync(0xffffffffu, u[1], 1);
    if (lane == 0)  u[0] = row[max(gc - 1, 0)];
    if (lane == 31) u[9] = row[min(gc + 8, WW - 1)];
}

__global__ __launch_bounds__(128, 8)
void max_kernel(const float* __restrict__ x) {
    __shared__ float wmax[4];
    const int ch = blockIdx.y;
    const int y0 = blockIdx.x * RSTRIP;
    const int gc = threadIdx.x * 8;
    const int lane = threadIdx.x & 31;
    const float* __restrict__ xc = x + (size_t)ch * (HH * WW);

    float X[3][10];
    ldrow10(xc + max(y0 - 1, 0) * WW, gc, lane, X[0]);
    ldrow10(xc + y0 * WW, gc, lane, X[1]);

    float m = 0.0f;
    #pragma unroll
    for (int i = 0; i < RSTRIP; i++) {
        const int ry = min(y0 + i + 1, HH - 1);
        ldrow10(xc + ry * WW, gc, lane, X[(i + 2) % 3]);
        const float* a = X[i % 3];
        const float* b = X[(i + 1) % 3];
        const float* c = X[(i + 2) % 3];

        float t[10], C[10];
        #pragma unroll
        for (int k = 0; k < 10; k++) { t[k] = a[k] + c[k]; C[k] = a[k] - c[k]; }

        #pragma unroll
        for (int j = 0; j < 8; j++) {
            float u = t[j] + t[j + 2];
            float p = fmaf(-4.0f, b[j + 1], u);
            float r = (b[j] + b[j + 2]) - t[j + 1];
            float r2 = r + r;
            float gxy = C[j + 2] - C[j];
            float m1 = fmaf(r2, r2, gxy * gxy);
            float det = fmaf(p, p, -m1);
            m = fmaxf(m, fabsf(det));
        }
    }

    #pragma unroll
    for (int off = 16; off > 0; off >>= 1)
        m = fmaxf(m, __shfl_xor_sync(0xffffffffu, m, off));
    if (lane == 0) wmax[threadIdx.x >> 5] = m;
    __syncthreads();
    if (threadIdx.x == 0) {
        m = fmaxf(fmaxf(wmax[0], wmax[1]), fmaxf(wmax[2], wmax[3]));
        g_bmax[ch * SLICES + blockIdx.x] = m;
    }
}

// ---------------------------------------------------------------------------
// Pass 2: scores + separable NMS + normalization, registers only.
// 8 output cols per thread. Depth-2 software pipeline on the aligned float4
// loads only (edges + shuffles at consume time). Reverse channel order for
// L2 reuse of max_kernel's most recent x traffic.
// ---------------------------------------------------------------------------
__device__ __forceinline__ void expand12(float4 m0, float4 m1,
                                         const float* __restrict__ row,
                                         int lane, int lcm2, int lcm1,
                                         int lcp8, int lcp9, float v[12]) {
    v[2] = m0.x; v[3] = m0.y; v[4] = m0.z; v[5] = m0.w;
    v[6] = m1.x; v[7] = m1.y; v[8] = m1.z; v[9] = m1.w;
    v[0]  = __shfl_up_sync(0xffffffffu, v[8], 1);   // prev lane x[gc-2]
    v[1]  = __shfl_up_sync(0xffffffffu, v[9], 1);   // prev lane x[gc-1]
    v[10] = __shfl_down_sync(0xffffffffu, v[2], 1); // next lane x[gc+8]
    v[11] = __shfl_down_sync(0xffffffffu, v[3], 1); // next lane x[gc+9]
    if (lane == 0)  { v[0]  = row[lcm2]; v[1]  = row[lcm1]; }
    if (lane == 31) { v[10] = row[lcp8]; v[11] = row[lcp9]; }
}

__global__ __launch_bounds__(128, 5)
void hessian_kernel(const float* __restrict__ x, float* __restrict__ out) {
    __shared__ float redsm[2];
    const int ch = (NCH - 1) - blockIdx.y;          // reverse channel order
    const int y0 = blockIdx.x * RSTRIP;
    const int gc = threadIdx.x * 8;
    const int lane = threadIdx.x & 31;
    const float* __restrict__ xc = x + (size_t)ch * (HH * WW);
    float* __restrict__ oc = out + (size_t)ch * (HH * WW);

    // Reduce the 64 per-slice maxima for this channel (L2-hit loads).
    if (threadIdx.x < SLICES) {
        float v = g_bmax[ch * SLICES + threadIdx.x];
        #pragma unroll
        for (int off = 16; off > 0; off >>= 1)
            v = fmaxf(v, __shfl_xor_sync(0xffffffffu, v, off));
        if ((threadIdx.x & 31) == 0) redsm[threadIdx.x >> 5] = v;
    }
    __syncthreads();
    const float inv = 1.0f / fmaxf(fmaxf(redsm[0], redsm[1]), 1e-6f);

    const int lcm2 = max(gc - 2, 0), lcm1 = max(gc - 1, 0);
    const int lcp8 = min(gc + 8, WW - 1), lcp9 = min(gc + 9, WW - 1);

    float X[3][12];                // x rows, cols gc-2..gc+9
    float s1[10], s2[10];          // previous two score rows (cols gc-1..gc+8)
    #pragma unroll
    for (int k = 0; k < 10; k++) { s1[k] = 0.0f; s2[k] = 0.0f; }

    // Prologue: rows y0-2, y0-1 loaded + expanded immediately.
    {
        const float* r0 = xc + max(y0 - 2, 0) * WW;
        float4 a0 = *reinterpret_cast<const float4*>(r0 + gc);
        float4 a1 = *reinterpret_cast<const float4*>(r0 + gc + 4);
        expand12(a0, a1, r0, lane, lcm2, lcm1, lcp8, lcp9, X[0]);
        const float* r1 = xc + max(y0 - 1, 0) * WW;
        a0 = *reinterpret_cast<const float4*>(r1 + gc);
        a1 = *reinterpret_cast<const float4*>(r1 + gc + 4);
        expand12(a0, a1, r1, lane, lcm2, lcm1, lcp8, lcp9, X[1]);
    }

    // Depth-2 pipeline: pending float4s for rows y0 and y0+1.
    const float* prow[2];
    float4 p0[2], p1[2];
    prow[0] = xc + y0 * WW;
    p0[0] = *reinterpret_cast<const float4*>(prow[0] + gc);
    p1[0] = *reinterpret_cast<const float4*>(prow[0] + gc + 4);
    prow[1] = xc + min(y0 + 1, HH - 1) * WW;
    p0[1] = *reinterpret_cast<const float4*>(prow[1] + gc);
    p1[1] = *reinterpret_cast<const float4*>(prow[1] + gc + 4);

    #pragma unroll
    for (int i = 0; i < RSTRIP + 2; i++) {
        const int sr = y0 - 1 + i;                  // score row produced this iter
        const int pb = i & 1;
        // Consume pending row y0+i.
        expand12(p0[pb], p1[pb], prow[pb], lane, lcm2, lcm1, lcp8, lcp9,
                 X[(2 + i) % 3]);
        // Prefetch row y0+i+2 (two iterations ahead).
        if (i < RSTRIP) {
            const float* rn = xc + min(y0 + i + 2, HH - 1) * WW;
            prow[pb] = rn;
            p0[pb] = *reinterpret_cast<const float4*>(rn + gc);
            p1[pb] = *reinterpret_cast<const float4*>(rn + gc + 4);
        }

        const float* a = X[i % 3];
        const float* b = X[(i + 1) % 3];
        const float* c = X[(i + 2) % 3];

        float t[12], C[12];
        #pragma unroll
        for (int k = 0; k < 12; k++) { t[k] = a[k] + c[k]; C[k] = a[k] - c[k]; }

        float sc[10];
        #pragma unroll
        for (int j = 0; j < 10; j++) {              // score cols gc-1+j
            float u = t[j] + t[j + 2];
            float p = fmaf(-4.0f, b[j + 1], u);
            float r = (b[j] + b[j + 2]) - t[j + 1];
            float r2 = r + r;
            float gxy = C[j + 2] - C[j];
            float m1 = fmaf(r2, r2, gxy * gxy);
            float det = fmaf(p, p, -m1);
            sc[j] = fmaxf(fabsf(det), 1e-6f);
        }
        // Column edges: score col -1 (thread 0) / col 1024 (thread 127).
        if (gc == 0)       sc[0] = -CUDART_INF_F;
        if (gc == WW - 8)  sc[9] = -CUDART_INF_F;
        // Row edges: only possible at unrolled iters 0 and RSTRIP+1.
        if ((i == 0 && sr < 0) || (i == RSTRIP + 1 && sr >= HH)) {
            #pragma unroll
            for (int k = 0; k < 10; k++) sc[k] = -CUDART_INF_F;
        }

        if (i >= 2) {
            const int y = sr - 1;                   // output row
            float cm[10];
            #pragma unroll
            for (int k = 0; k < 10; k++)
                cm[k] = fmaxf(fmaxf(s2[k], s1[k]), sc[k]);
            float ov[8];
            #pragma unroll
            for (int k = 0; k < 8; k++) {
                float pmax = fmaxf(fmaxf(cm[k], cm[k + 1]), cm[k + 2]);
                float sv = s1[k + 1];
                ov[k] = (sv == pmax) ? sv * inv : 0.0f;
            }
            float4 o0, o1;
            o0.x = ov[0]; o0.y = ov[1]; o0.z = ov[2]; o0.w = ov[3];
            o1.x = ov[4]; o1.y = ov[5]; o1.z = ov[6]; o1.w = ov[7];
            float* orow = oc + (size_t)y * WW + gc;
            *reinterpret_cast<float4*>(orow) = o0;
            *reinterpret_cast<float4*>(orow + 4) = o1;
        }

        #pragma unroll
        for (int k = 0; k < 10; k++) { s2[k] = s1[k]; s1[k] = sc[k]; }
    }
}

extern "C" void kernel_launch(void* const* d_in, const int* in_sizes, int n_in,
                              void* d_out, int out_size) {
    const float* x = (const float*)d_in[0];
    float* out = (float*)d_out;

    dim3 mgrd(SLICES, NCH);
    max_kernel<<<mgrd, 128>>>(x);

    dim3 hgrd(HH / RSTRIP, NCH);
    hessian_kernel<<<hgrd, 128>>>(x, out);
}